// round 13
// baseline (speedup 1.0000x reference)
#include <cuda_runtime.h>

#define BN 24
#define BM 128
#define BK 64
#define NITER 8
#define NFIX 12
#define NACT 12
#define PIF 3.14159274101257324f   // float32(np.pi)
#define BLOCK 256
#define GPB (BLOCK / 16)           // 16 batches (16-lane groups) per block

// ---------------------------------------------------------------------------
// packed FFMA2: {dx,dy} = {ax,ay}*{bx,by} + {cx,cy}  (bit-exact 2x IEEE FFMA)
// floats live in normal registers; pack/unpack movs coalesce when the pairs
// are register-adjacent (LDG.128/LDS.64 results, repeated pair outputs).
// ---------------------------------------------------------------------------
__device__ __forceinline__ void ffma2(float& dx, float& dy,
                                      float ax, float ay,
                                      float bx, float by,
                                      float cx, float cy)
{
    asm("{\n\t"
        ".reg .b64 ra, rb, rc, rd;\n\t"
        "mov.b64 ra, {%2, %3};\n\t"
        "mov.b64 rb, {%4, %5};\n\t"
        "mov.b64 rc, {%6, %7};\n\t"
        "fma.rn.f32x2 rd, ra, rb, rc;\n\t"
        "mov.b64 {%0, %1}, rd;\n\t"
        "}"
        : "=f"(dx), "=f"(dy)
        : "f"(ax), "f"(ay), "f"(bx), "f"(by), "f"(cx), "f"(cy));
}

// ---------------------------------------------------------------------------
__device__ __forceinline__ float dot4(float4 a, float4 b) {
    return fmaf(a.x, b.x, fmaf(a.y, b.y, fmaf(a.z, b.z, a.w * b.w)));
}
__device__ __forceinline__ float4 mul4(float4 a, float s) {
    return make_float4(a.x * s, a.y * s, a.z * s, a.w * s);
}
__device__ __forceinline__ float4 fma4(float4 a, float s, float4 c) {
    return make_float4(fmaf(a.x, s, c.x), fmaf(a.y, s, c.y),
                       fmaf(a.z, s, c.z), fmaf(a.w, s, c.w));
}
__device__ __forceinline__ float gsum16(float v) {
    v += __shfl_xor_sync(0xffffffffu, v, 8);
    v += __shfl_xor_sync(0xffffffffu, v, 4);
    v += __shfl_xor_sync(0xffffffffu, v, 2);
    v += __shfl_xor_sync(0xffffffffu, v, 1);
    return v;
}
__device__ __forceinline__ void gsum16_2(float& a, float& b) {
    a += __shfl_xor_sync(0xffffffffu, a, 8); b += __shfl_xor_sync(0xffffffffu, b, 8);
    a += __shfl_xor_sync(0xffffffffu, a, 4); b += __shfl_xor_sync(0xffffffffu, b, 4);
    a += __shfl_xor_sync(0xffffffffu, a, 2); b += __shfl_xor_sync(0xffffffffu, b, 2);
    a += __shfl_xor_sync(0xffffffffu, a, 1); b += __shfl_xor_sync(0xffffffffu, b, 1);
}
__device__ __forceinline__ float wsum32(float v) {
    v += __shfl_xor_sync(0xffffffffu, v, 16);
    return gsum16(v);
}
__device__ __forceinline__ float out_angle(float co) {
    float c = fminf(fmaxf(-co, -1.0f + 1e-6f), 1.0f - 1e-6f);
    return acosf(c) / PIF;
}

// ---------------------------------------------------------------------------
// One 16-lane group per batch element; lane owns comps 4*gl .. 4*gl+3.
// ---------------------------------------------------------------------------
__global__ void __launch_bounds__(BLOCK) mix_kernel(
    const float* __restrict__ z,
    const float* __restrict__ S,
    const float* __restrict__ Vr,
    const int* __restrict__ isin,
    float* __restrict__ out,
    int B)
{
    // Duplicated-pair Gram rows 12..23: Gdup2[r*BN + c] = {G[12+r][c], same}
    __shared__ __align__(16) float2 Gdup2[NACT * BN];

    const int tid  = threadIdx.x;
    const int wlid = tid & 31;
    const int wid  = tid >> 5;

    // ---- phase 0: 288 Gram entries, warp-cooperative (lanes span M=128) ----
    const float4* S4 = (const float4*)S;
#pragma unroll
    for (int e = wid; e < NACT * BN; e += BLOCK / 32) {
        int i = NFIX + e / BN, j = e % BN;
        float part = dot4(S4[i * 32 + wlid], S4[j * 32 + wlid]);
        float g = wsum32(part);
        if (wlid == 0) Gdup2[e] = make_float2(g, g);
    }
    __syncthreads();

    const int grp = tid >> 4;
    const int gl  = tid & 15;
    int b = blockIdx.x * GPB + grp;
    if (b >= B) b = B - 1;    // duplicate work, deterministic

    const float4* vrow = (const float4*)Vr + (size_t)b * BN * (BK / 4);
    float*        outb = out + (size_t)b * BN;

    unsigned mask = 0;
#pragma unroll
    for (int n = 0; n < BN; n++)
        mask |= (isin[b * BN + n] > 0) ? (1u << n) : 0u;

    // ---- v0 ----
    float4 f0  = vrow[gl];
    float  ss0 = gsum16(dot4(f0, f0));
    float4 v0  = mul4(f0, rsqrtf(fmaxf(ss0, 1e-30f)));

    if (mask == 0xFFFu) {
        // ================= FAST PATH: inputs are rows 0..11 =================
        float nv0 = gsum16(dot4(v0, v0));      // |v0|^2 (~1), row-0 output
        if (gl == 0) outb[0] = out_angle(nv0);

        float4 h[NACT];
#pragma unroll
        for (int ii = 0; ii < NACT; ii++)
            h[ii] = mul4(v0, Gdup2[ii * BN + 0].x);

        // fixed input rows 1..11
#pragma unroll
        for (int n = 1; n < NFIX; n++) {
            float4 f  = vrow[n * 16 + gl];
            float  ss = dot4(f, f);
            float  fv = dot4(f, v0);
            gsum16_2(ss, fv);
            float ww = fmaf(-fv * fv, 2.0f - nv0, ss);   // |f - fv*v0|^2
            float iu = rsqrtf(fmaxf(ww, 1e-24f));
            float4 u = mul4(fma4(v0, -fv, f), iu);
            float sz, cz;
            __sincosf(PIF * z[b * BN + n], &sz, &cz);
            float4 vv = fma4(v0, -cz, mul4(u, sz));
            float co = fmaf(-cz, nv0, sz * iu * fv * (1.0f - nv0));
            if (gl == 0) outb[n] = out_angle(co);
#pragma unroll
            for (int ii = 0; ii < NACT; ii++) {
                float2 wp = Gdup2[ii * BN + n];   // LDS.64 -> adjacent pair
                ffma2(h[ii].x, h[ii].y, vv.x, vv.y, wp.x, wp.y, h[ii].x, h[ii].y);
                ffma2(h[ii].z, h[ii].w, vv.z, vv.w, wp.x, wp.y, h[ii].z, h[ii].w);
            }
        }

        // free rows 12..23 (paired reductions)
        float4 A[NACT];
#pragma unroll
        for (int jj = 0; jj < NACT; jj += 2) {
            float4 fa = vrow[(NFIX + jj) * 16 + gl];
            float4 fb = vrow[(NFIX + jj + 1) * 16 + gl];
            float  sa = dot4(fa, fa);
            float  sb = dot4(fb, fb);
            gsum16_2(sa, sb);
            A[jj]     = mul4(fa, rsqrtf(fmaxf(sa, 1e-30f)));
            A[jj + 1] = mul4(fb, rsqrtf(fmaxf(sb, 1e-30f)));
        }

        // ---- software-pipelined Gauss–Seidel, packed FFMA2 q-build ----
        // Invariant: p = h[ii] + sum_{jj!=ii} G[ii][jj]*A[jj]  (GS recency).
        float4 p;
        {
            const float4* gr = (const float4*)(Gdup2 + 0 * BN + NFIX);
            float4 q = h[0];
#pragma unroll
            for (int jj = 1; jj < NACT; jj++) {
                float4 gj = gr[jj >> 1];
                float px = (jj & 1) ? gj.z : gj.x;
                float py = (jj & 1) ? gj.w : gj.y;
                ffma2(q.x, q.y, A[jj].x, A[jj].y, px, py, q.x, q.y);
                ffma2(q.z, q.w, A[jj].z, A[jj].w, px, py, q.z, q.w);
            }
            p = q;
        }

        for (int t = 0; t < NITER; t++) {
#pragma unroll
            for (int ii = 0; ii < NACT; ii++) {
                // launch this step's reduction first...
                float s = gsum16(dot4(p, p));

                // ...hide its latency building next step's partial sum
                const int nx = (ii + 1) % NACT;
                const float4* gr = (const float4*)(Gdup2 + nx * BN + NFIX);
                float4 q = h[nx];
#pragma unroll
                for (int jj = 0; jj < NACT; jj++) {
                    if (jj == nx || jj == ii) continue;
                    float4 gj = gr[jj >> 1];
                    float px = (jj & 1) ? gj.z : gj.x;
                    float py = (jj & 1) ? gj.w : gj.y;
                    ffma2(q.x, q.y, A[jj].x, A[jj].y, px, py, q.x, q.y);
                    ffma2(q.z, q.w, A[jj].z, A[jj].w, px, py, q.z, q.w);
                }

                float  inv = -rsqrtf(s);      // s = |p|^2 > 0
                float4 An  = mul4(p, inv);
                A[ii] = An;
                // add the deferred G[nx][ii]*A[ii] term
                float4 gi = gr[ii >> 1];
                float wx = (ii & 1) ? gi.z : gi.x;
                float wy = (ii & 1) ? gi.w : gi.y;
                ffma2(q.x, q.y, An.x, An.y, wx, wy, q.x, q.y);
                ffma2(q.z, q.w, An.z, An.w, wx, wy, q.z, q.w);
                p = q;
            }
        }

        // active outputs (paired reductions)
#pragma unroll
        for (int ii = 0; ii < NACT; ii += 2) {
            float c0 = dot4(A[ii], v0);
            float c1 = dot4(A[ii + 1], v0);
            gsum16_2(c0, c1);
            if (gl == 0) {
                outb[NFIX + ii]     = out_angle(c0);
                outb[NFIX + ii + 1] = out_angle(c1);
            }
        }
    } else {
        // ============ GENERIC PATH (any mask) — cold =========================
        float Gc[BN * BN];
#pragma unroll 1
        for (int e = 0; e < BN * BN; e++) {
            int i = e / BN, j = e % BN;
            float part = dot4(S4[i * 32 + gl],      S4[j * 32 + gl]) +
                         dot4(S4[i * 32 + 16 + gl], S4[j * 32 + 16 + gl]);
            Gc[e] = gsum16(part);
        }

        float4 Vl[BN];
        Vl[0] = v0;
        float nv0g = gsum16(dot4(v0, v0));
#pragma unroll 1
        for (int n = 1; n < BN; n++) {
            float4 f  = vrow[n * 16 + gl];
            float  ss = dot4(f, f);
            float  fv = dot4(f, v0);
            gsum16_2(ss, fv);
            float4 r = mul4(f, rsqrtf(fmaxf(ss, 1e-30f)));
            if ((mask >> n) & 1u) {
                float ww = fmaf(-fv * fv, 2.0f - nv0g, ss);
                float iu = rsqrtf(fmaxf(ww, 1e-24f));
                float4 u = mul4(fma4(v0, -fv, f), iu);
                float sz, cz;
                __sincosf(PIF * z[b * BN + n], &sz, &cz);
                Vl[n] = fma4(v0, -cz, mul4(u, sz));
            } else {
                Vl[n] = r;
            }
        }
#pragma unroll 1
        for (int t = 0; t < NITER; t++) {
#pragma unroll 1
            for (int i = 0; i < BN; i++) {
                if ((mask >> i) & 1u) continue;
                float4 acc = make_float4(0.f, 0.f, 0.f, 0.f);
#pragma unroll 1
                for (int n = 0; n < BN; n++)
                    acc = fma4(Vl[n], Gc[i * BN + n], acc);
                acc = fma4(Vl[i], -Gc[i * BN + i], acc);
                float sg = gsum16(dot4(acc, acc));
                Vl[i] = mul4(acc, -rsqrtf(fmaxf(sg, 1e-30f)));
            }
        }
#pragma unroll 1
        for (int n = 0; n < BN; n++) {
            float co = gsum16(dot4(Vl[n], v0));
            if (gl == 0) outb[n] = out_angle(co);
        }
    }
}

// ---------------------------------------------------------------------------
extern "C" void kernel_launch(void* const* d_in, const int* in_sizes, int n_in,
                              void* d_out, int out_size) {
    const float* z    = (const float*)d_in[0];   // (B, 24)
    const float* S    = (const float*)d_in[1];   // (24, 128)
    const float* Vr   = (const float*)d_in[2];   // (B, 24, 64)
    const int*   isin = (const int*)d_in[3];     // (B, 24)
    float*       out  = (float*)d_out;           // (B, 24)

    const int B = in_sizes[0] / BN;
    const int grid = (B + GPB - 1) / GPB;
    mix_kernel<<<grid, BLOCK>>>(z, S, Vr, isin, out, B);
}

// round 14
// speedup vs baseline: 1.4360x; 1.4360x over previous
#include <cuda_runtime.h>

#define BN 24
#define BM 128
#define BK 64
#define NITER 8
#define NFIX 12
#define NACT 12
#define PIF 3.14159274101257324f   // float32(np.pi)
#define BLOCK 256
#define GPB (BLOCK / 16)           // 16 batches (16-lane groups) per block

// ---------------------------------------------------------------------------
__device__ __forceinline__ float dot4(float4 a, float4 b) {
    return fmaf(a.x, b.x, fmaf(a.y, b.y, fmaf(a.z, b.z, a.w * b.w)));
}
__device__ __forceinline__ float4 mul4(float4 a, float s) {
    return make_float4(a.x * s, a.y * s, a.z * s, a.w * s);
}
__device__ __forceinline__ float4 fma4(float4 a, float s, float4 c) {
    return make_float4(fmaf(a.x, s, c.x), fmaf(a.y, s, c.y),
                       fmaf(a.z, s, c.z), fmaf(a.w, s, c.w));
}
__device__ __forceinline__ float gsum16(float v) {
    v += __shfl_xor_sync(0xffffffffu, v, 8);
    v += __shfl_xor_sync(0xffffffffu, v, 4);
    v += __shfl_xor_sync(0xffffffffu, v, 2);
    v += __shfl_xor_sync(0xffffffffu, v, 1);
    return v;
}
__device__ __forceinline__ void gsum16_2(float& a, float& b) {
    a += __shfl_xor_sync(0xffffffffu, a, 8); b += __shfl_xor_sync(0xffffffffu, b, 8);
    a += __shfl_xor_sync(0xffffffffu, a, 4); b += __shfl_xor_sync(0xffffffffu, b, 4);
    a += __shfl_xor_sync(0xffffffffu, a, 2); b += __shfl_xor_sync(0xffffffffu, b, 2);
    a += __shfl_xor_sync(0xffffffffu, a, 1); b += __shfl_xor_sync(0xffffffffu, b, 1);
}
__device__ __forceinline__ float wsum32(float v) {
    v += __shfl_xor_sync(0xffffffffu, v, 16);
    return gsum16(v);
}
__device__ __forceinline__ float out_angle(float co) {
    float c = fminf(fmaxf(-co, -1.0f + 1e-6f), 1.0f - 1e-6f);
    return acosf(c) / PIF;
}

// ---------------------------------------------------------------------------
// One 16-lane group per batch element; lane owns comps 4*gl .. 4*gl+3.
// ---------------------------------------------------------------------------
__global__ void __launch_bounds__(BLOCK) mix_kernel(
    const float* __restrict__ z,
    const float* __restrict__ S,
    const float* __restrict__ Vr,
    const int* __restrict__ isin,
    float* __restrict__ out,
    int B)
{
    // Gram rows 12..23: Gs2[r*BN + c] = G[12+r][c]
    __shared__ __align__(16) float Gs2[NACT * BN];

    const int tid  = threadIdx.x;
    const int wlid = tid & 31;
    const int wid  = tid >> 5;

    // ---- phase 0: 288 Gram entries, warp-cooperative (lanes span M=128) ----
    const float4* S4 = (const float4*)S;
#pragma unroll
    for (int e = wid; e < NACT * BN; e += BLOCK / 32) {
        int i = NFIX + e / BN, j = e % BN;
        float part = dot4(S4[i * 32 + wlid], S4[j * 32 + wlid]);
        float g = wsum32(part);
        if (wlid == 0) Gs2[e] = g;
    }
    __syncthreads();

    const int grp = tid >> 4;
    const int gl  = tid & 15;
    int b = blockIdx.x * GPB + grp;
    if (b >= B) b = B - 1;    // duplicate work, deterministic

    const float4* vrow = (const float4*)Vr + (size_t)b * BN * (BK / 4);
    float*        outb = out + (size_t)b * BN;

    unsigned mask = 0;
#pragma unroll
    for (int n = 0; n < BN; n++)
        mask |= (isin[b * BN + n] > 0) ? (1u << n) : 0u;

    // ---- v0 ----
    float4 f0  = vrow[gl];
    float  ss0 = gsum16(dot4(f0, f0));
    float4 v0  = mul4(f0, rsqrtf(fmaxf(ss0, 1e-30f)));

    if (mask == 0xFFFu) {
        // ================= FAST PATH: inputs are rows 0..11 =================
        float nv0 = gsum16(dot4(v0, v0));      // |v0|^2 (~1), row-0 output
        if (gl == 0) outb[0] = out_angle(nv0);

        float4 h[NACT];
#pragma unroll
        for (int ii = 0; ii < NACT; ii++)
            h[ii] = mul4(v0, Gs2[ii * BN + 0]);

        // fixed input rows 1..11
#pragma unroll
        for (int n = 1; n < NFIX; n++) {
            float4 f  = vrow[n * 16 + gl];
            float  ss = dot4(f, f);
            float  fv = dot4(f, v0);
            gsum16_2(ss, fv);
            float ww = fmaf(-fv * fv, 2.0f - nv0, ss);   // |f - fv*v0|^2
            float iu = rsqrtf(fmaxf(ww, 1e-24f));
            float4 u = mul4(fma4(v0, -fv, f), iu);
            float sz, cz;
            __sincosf(PIF * z[b * BN + n], &sz, &cz);
            float4 vv = fma4(v0, -cz, mul4(u, sz));
            float co = fmaf(-cz, nv0, sz * iu * fv * (1.0f - nv0));
            if (gl == 0) outb[n] = out_angle(co);
#pragma unroll
            for (int ii = 0; ii < NACT; ii++)
                h[ii] = fma4(vv, Gs2[ii * BN + n], h[ii]);
        }

        // free rows 12..23 (paired reductions)
        float4 A[NACT];
#pragma unroll
        for (int jj = 0; jj < NACT; jj += 2) {
            float4 fa = vrow[(NFIX + jj) * 16 + gl];
            float4 fb = vrow[(NFIX + jj + 1) * 16 + gl];
            float  sa = dot4(fa, fa);
            float  sb = dot4(fb, fb);
            gsum16_2(sa, sb);
            A[jj]     = mul4(fa, rsqrtf(fmaxf(sa, 1e-30f)));
            A[jj + 1] = mul4(fb, rsqrtf(fmaxf(sb, 1e-30f)));
        }

        // ---- 2-deep software-pipelined Gauss–Seidel ----
        // At the top of step ii:
        //   p  = full gradient of row ii (correct GS recency)
        //   r1 = gradient of row ii+1, missing ONLY the A[ii] term
        // Step body:
        //   - launch reduction of |p|^2
        //   - build r2 = gradient of row ii+2 missing A[ii], A[ii+1]
        //     (independent of the reduction -> fills the latency shadow)
        //   - A[ii] = -rsqrt(s)*p
        //   - p  <- r1 + G[ii+1][ii]*A[ii]
        //   - r1 <- r2 + G[ii+2][ii]*A[ii]   (still missing A[ii+1], by design)
        float4 p, r1;
        {
            const float4* gr = (const float4*)&Gs2[0 * BN + NFIX];
            float4 w0 = gr[0], w1 = gr[1], w2 = gr[2];
            const float wv[NACT] = { w0.x, w0.y, w0.z, w0.w,
                                     w1.x, w1.y, w1.z, w1.w,
                                     w2.x, w2.y, w2.z, w2.w };
            p = h[0];
#pragma unroll
            for (int jj = 1; jj < NACT; jj++) p = fma4(A[jj], wv[jj], p);

            const float4* g1 = (const float4*)&Gs2[1 * BN + NFIX];
            float4 x0 = g1[0], x1 = g1[1], x2 = g1[2];
            const float wv1[NACT] = { x0.x, x0.y, x0.z, x0.w,
                                      x1.x, x1.y, x1.z, x1.w,
                                      x2.x, x2.y, x2.z, x2.w };
            r1 = h[1];
#pragma unroll
            for (int jj = 2; jj < NACT; jj++) r1 = fma4(A[jj], wv1[jj], r1);
        }

        for (int t = 0; t < NITER; t++) {
#pragma unroll
            for (int ii = 0; ii < NACT; ii++) {
                // launch this step's reduction first...
                float s = gsum16(dot4(p, p));

                // ...shadow: build row ii+2's partial sum (9 terms)
                const int n1 = (ii + 1) % NACT;
                const int n2 = (ii + 2) % NACT;
                const float4* gr2 = (const float4*)&Gs2[n2 * BN + NFIX];
                float4 w0 = gr2[0], w1 = gr2[1], w2 = gr2[2];
                const float wv2[NACT] = { w0.x, w0.y, w0.z, w0.w,
                                          w1.x, w1.y, w1.z, w1.w,
                                          w2.x, w2.y, w2.z, w2.w };
                float4 r2 = h[n2];
#pragma unroll
                for (int jj = 0; jj < NACT; jj++) {
                    if (jj == ii || jj == n1 || jj == n2) continue;
                    r2 = fma4(A[jj], wv2[jj], r2);
                }
                const float w1i = Gs2[n1 * BN + NFIX + ii];  // G[n1][ii]

                float  inv = -rsqrtf(s);      // s = |p|^2 > 0
                float4 An  = mul4(p, inv);
                A[ii] = An;
                p  = fma4(An, w1i,     r1);
                r1 = fma4(An, wv2[ii], r2);
            }
        }

        // active outputs (paired reductions)
#pragma unroll
        for (int ii = 0; ii < NACT; ii += 2) {
            float c0 = dot4(A[ii], v0);
            float c1 = dot4(A[ii + 1], v0);
            gsum16_2(c0, c1);
            if (gl == 0) {
                outb[NFIX + ii]     = out_angle(c0);
                outb[NFIX + ii + 1] = out_angle(c1);
            }
        }
    } else {
        // ============ GENERIC PATH (any mask) — cold =========================
        float Gc[BN * BN];
#pragma unroll 1
        for (int e = 0; e < BN * BN; e++) {
            int i = e / BN, j = e % BN;
            float part = dot4(S4[i * 32 + gl],      S4[j * 32 + gl]) +
                         dot4(S4[i * 32 + 16 + gl], S4[j * 32 + 16 + gl]);
            Gc[e] = gsum16(part);
        }

        float4 Vl[BN];
        Vl[0] = v0;
        float nv0g = gsum16(dot4(v0, v0));
#pragma unroll 1
        for (int n = 1; n < BN; n++) {
            float4 f  = vrow[n * 16 + gl];
            float  ss = dot4(f, f);
            float  fv = dot4(f, v0);
            gsum16_2(ss, fv);
            float4 r = mul4(f, rsqrtf(fmaxf(ss, 1e-30f)));
            if ((mask >> n) & 1u) {
                float ww = fmaf(-fv * fv, 2.0f - nv0g, ss);
                float iu = rsqrtf(fmaxf(ww, 1e-24f));
                float4 u = mul4(fma4(v0, -fv, f), iu);
                float sz, cz;
                __sincosf(PIF * z[b * BN + n], &sz, &cz);
                Vl[n] = fma4(v0, -cz, mul4(u, sz));
            } else {
                Vl[n] = r;
            }
        }
#pragma unroll 1
        for (int t = 0; t < NITER; t++) {
#pragma unroll 1
            for (int i = 0; i < BN; i++) {
                if ((mask >> i) & 1u) continue;
                float4 acc = make_float4(0.f, 0.f, 0.f, 0.f);
#pragma unroll 1
                for (int n = 0; n < BN; n++)
                    acc = fma4(Vl[n], Gc[i * BN + n], acc);
                acc = fma4(Vl[i], -Gc[i * BN + i], acc);
                float sg = gsum16(dot4(acc, acc));
                Vl[i] = mul4(acc, -rsqrtf(fmaxf(sg, 1e-30f)));
            }
        }
#pragma unroll 1
        for (int n = 0; n < BN; n++) {
            float co = gsum16(dot4(Vl[n], v0));
            if (gl == 0) outb[n] = out_angle(co);
        }
    }
}

// ---------------------------------------------------------------------------
extern "C" void kernel_launch(void* const* d_in, const int* in_sizes, int n_in,
                              void* d_out, int out_size) {
    const float* z    = (const float*)d_in[0];   // (B, 24)
    const float* S    = (const float*)d_in[1];   // (24, 128)
    const float* Vr   = (const float*)d_in[2];   // (B, 24, 64)
    const int*   isin = (const int*)d_in[3];     // (B, 24)
    float*       out  = (float*)d_out;           // (B, 24)

    const int B = in_sizes[0] / BN;
    const int grid = (B + GPB - 1) / GPB;
    mix_kernel<<<grid, BLOCK>>>(z, S, Vr, isin, out, B);
}